// round 2
// baseline (speedup 1.0000x reference)
#include <cuda_runtime.h>
#include <cstdint>

// Morton-order gather: out[k] = x[i][j], j = compacted even bits of k,
// i = compacted odd bits of k, per 256x256 image (512 images).
//
// Each thread produces 16 consecutive outputs (k ≡ 0 mod 16), which map to a
// 4x4 input block (j, i both ≡ 0 mod 4):
//   k offset o = o0 + 2*o1 + 4*o2 + 8*o3  ->  x[i + o1 + 2*o3][j + o0 + 2*o2]
// So: 4x LDG.128 (rows i..i+3, cols j..j+3) + 4x STG.128 (64B contiguous out).
// Warp-wide each LDG.128 covers 4 full 128B lines; stores are 2KB contiguous.

__global__ __launch_bounds__(256) void morton_gather16_kernel(
    const float* __restrict__ in, float* __restrict__ out)
{
    unsigned t = blockIdx.x * 256u + threadIdx.x;
    unsigned g = t << 4;                 // output flat element index (mult of 16)
    unsigned k = g & 0xFFFFu;            // index within one 256x256 image
    unsigned img = g >> 16;              // which (b, c) image

    // Bit-deinterleave k (low 4 bits are zero): even bits -> j, odd bits -> i.
    unsigned e = k & 0x5555u;
    unsigned o = (k >> 1) & 0x5555u;
    e = (e | (e >> 1)) & 0x3333u;
    e = (e | (e >> 2)) & 0x0F0Fu;
    e = (e | (e >> 4)) & 0x00FFu;
    o = (o | (o >> 1)) & 0x3333u;
    o = (o | (o >> 2)) & 0x0F0Fu;
    o = (o | (o >> 4)) & 0x00FFu;
    unsigned j = e;                      // column, multiple of 4
    unsigned i = o;                      // row,    multiple of 4

    const float* base = in + ((size_t)img << 16) + (i << 8) + j;
    // Four independent 16B loads from rows i..i+3 (full MLP before any store).
    float4 a = *reinterpret_cast<const float4*>(base);
    float4 b = *reinterpret_cast<const float4*>(base + 256);
    float4 c = *reinterpret_cast<const float4*>(base + 512);
    float4 d = *reinterpret_cast<const float4*>(base + 768);

    float4* dst = reinterpret_cast<float4*>(out + g);
    // o=0..3:   x[i][j],   x[i][j+1],   x[i+1][j],   x[i+1][j+1]
    dst[0] = make_float4(a.x, a.y, b.x, b.y);
    // o=4..7:   cols +2
    dst[1] = make_float4(a.z, a.w, b.z, b.w);
    // o=8..11:  rows +2
    dst[2] = make_float4(c.x, c.y, d.x, d.y);
    // o=12..15: rows +2, cols +2
    dst[3] = make_float4(c.z, c.w, d.z, d.w);
}

extern "C" void kernel_launch(void* const* d_in, const int* in_sizes, int n_in,
                              void* d_out, int out_size)
{
    const float* in = (const float*)d_in[0];
    float* out = (float*)d_out;
    // total elements = 8*64*256*256 = 33,554,432; 16 per thread
    const unsigned total_threads = 33554432u / 16u;  // 2,097,152
    const unsigned block = 256u;
    const unsigned grid = total_threads / block;     // 8,192
    morton_gather16_kernel<<<grid, block>>>(in, out);
}

// round 3
// speedup vs baseline: 1.1356x; 1.1356x over previous
#include <cuda_runtime.h>
#include <cstdint>

// Morton-order gather, 512 fp32 images of 256x256.
// out[k] = x[i][j], j = compacted even bits of k, i = compacted odd bits.
//
// Warp handles 512 consecutive outputs. Thread (lane l) produces 4 float4
// outputs at g_n = wb + n*128 + l*4 (n=0..3): every STG.128 instruction is
// 512B lane-contiguous (identical pattern to the R1 kernel that measured
// best). Each float4 output needs a 2x2 input block -> 2 float2 loads.
// All 8 loads are issued before any store -> MLP=8 per thread (vs 2 in R1)
// to hide DRAM latency.
//
// Morton offsets: k-bit2->j1, bit3->i1, bit4->j2, bit5->i2, bit6->j3,
// bit7->i3, bit8->j4. So n&1 adds +8 to i, n>>1 adds +16 to j.

__global__ __launch_bounds__(256) void morton_gather_mlp8_kernel(
    const float* __restrict__ in, float* __restrict__ out)
{
    unsigned t = blockIdx.x * 256u + threadIdx.x;
    unsigned lane = t & 31u;
    unsigned wb = (t >> 5) << 9;          // warp's first output element (mult of 512)
    unsigned img = wb >> 16;              // whole warp inside one image (512 | 65536)
    unsigned k0 = (wb & 0xFFFFu) + (lane << 2);  // this thread's n=0 output index

    // Deinterleave k0: even bits -> j, odd bits -> i (low 2 bits of k0 are 0).
    unsigned e = k0 & 0x5555u;
    unsigned o = (k0 >> 1) & 0x5555u;
    e = (e | (e >> 1)) & 0x3333u;
    e = (e | (e >> 2)) & 0x0F0Fu;
    e = (e | (e >> 4)) & 0x00FFu;
    o = (o | (o >> 1)) & 0x3333u;
    o = (o | (o >> 2)) & 0x0F0Fu;
    o = (o | (o >> 4)) & 0x00FFu;
    unsigned j = e;                       // column (even)
    unsigned i = o;                       // row    (even)

    const float* base = in + ((size_t)img << 16) + (i << 8) + j;

    // 8 independent float2 loads (rows {i, i+1} x {+0,+8}, cols {j, j+16}).
    // n=0: (+0,+0)  n=1: (+8 rows, +0)  n=2: (+0, +16 cols)  n=3: (+8, +16)
    float2 a0 = *reinterpret_cast<const float2*>(base);
    float2 a1 = *reinterpret_cast<const float2*>(base + 256);
    float2 b0 = *reinterpret_cast<const float2*>(base + 8 * 256);
    float2 b1 = *reinterpret_cast<const float2*>(base + 9 * 256);
    float2 c0 = *reinterpret_cast<const float2*>(base + 16);
    float2 c1 = *reinterpret_cast<const float2*>(base + 256 + 16);
    float2 d0 = *reinterpret_cast<const float2*>(base + 8 * 256 + 16);
    float2 d1 = *reinterpret_cast<const float2*>(base + 9 * 256 + 16);

    float* o0 = out + wb + lane * 4u;
    *reinterpret_cast<float4*>(o0)       = make_float4(a0.x, a0.y, a1.x, a1.y);
    *reinterpret_cast<float4*>(o0 + 128) = make_float4(b0.x, b0.y, b1.x, b1.y);
    *reinterpret_cast<float4*>(o0 + 256) = make_float4(c0.x, c0.y, c1.x, c1.y);
    *reinterpret_cast<float4*>(o0 + 384) = make_float4(d0.x, d0.y, d1.x, d1.y);
}

extern "C" void kernel_launch(void* const* d_in, const int* in_sizes, int n_in,
                              void* d_out, int out_size)
{
    const float* in = (const float*)d_in[0];
    float* out = (float*)d_out;
    // total elements = 33,554,432; 16 per thread
    const unsigned total_threads = 33554432u / 16u;  // 2,097,152
    const unsigned block = 256u;
    const unsigned grid = total_threads / block;     // 8,192
    morton_gather_mlp8_kernel<<<grid, block>>>(in, out);
}